// round 1
// baseline (speedup 1.0000x reference)
#include <cuda_runtime.h>
#include <math.h>

#define NV 786432
#define KS 5
#define NFOUT 32

// Scratch (static device globals; no allocations allowed)
__device__ float g_t0[(size_t)NV * NFOUT];
__device__ float g_t1[(size_t)NV * NFOUT];
__device__ float g_t2[(size_t)NV * NFOUT];
__device__ float g_h [(size_t)NV * NFOUT];

// ---------------------------------------------------------------------------
// k=0 GEMM: out[v,o] = bias[o] + sum_f x[v,f] * W[f*K+0, o]
// warp per vertex, lane = output channel
// ---------------------------------------------------------------------------
template<int FIN>
__global__ void gemm_init_kernel(const float* __restrict__ x, const float* __restrict__ W,
                                 const float* __restrict__ bias, float* __restrict__ out) {
    __shared__ float Wsh[FIN * NFOUT];
    int tid = threadIdx.x;
    for (int i = tid; i < FIN * NFOUT; i += blockDim.x) {
        int f = i >> 5, o = i & 31;
        Wsh[i] = W[(f * KS) * NFOUT + o];
    }
    __syncthreads();
    int v = (blockIdx.x * blockDim.x + tid) >> 5;
    int o = tid & 31;
    if (v >= NV) return;
    const float* xr = x + (size_t)v * FIN;
    float acc = __ldg(bias + o);
#pragma unroll
    for (int f = 0; f < FIN; f++)
        acc += xr[f] * Wsh[f * NFOUT + o];
    out[(size_t)v * NFOUT + o] = acc;
}

// ---------------------------------------------------------------------------
// Recurrence combine + GEMM accumulate:
//   if tprev: t_k = 2*raw - tprev (written back to traw)
//   out[v,o] += sum_f t_k[v,f] * W[f*K+k, o]
// warp per vertex, lane = output channel
// ---------------------------------------------------------------------------
template<int FIN>
__global__ void combine_gemm_kernel(float* __restrict__ traw, const float* __restrict__ tprev,
                                    const float* __restrict__ W, float* __restrict__ out, int k) {
    __shared__ float Wsh[FIN * NFOUT];
    int tid = threadIdx.x;
    for (int i = tid; i < FIN * NFOUT; i += blockDim.x) {
        int f = i >> 5, o = i & 31;
        Wsh[i] = W[(f * KS + k) * NFOUT + o];
    }
    __syncthreads();
    int v = (blockIdx.x * blockDim.x + tid) >> 5;
    int o = tid & 31;
    if (v >= NV) return;
    float* rr = traw + (size_t)v * FIN;
    float acc = out[(size_t)v * NFOUT + o];
    if (tprev != nullptr) {
        const float* pp = tprev + (size_t)v * FIN;
        float tk_lane = 0.0f;
#pragma unroll
        for (int f = 0; f < FIN; f++) {
            float tk = 2.0f * rr[f] - pp[f];
            acc += tk * Wsh[f * NFOUT + o];
            if (f == o) tk_lane = tk;
        }
        // all loads of rr[] above precede this store in the warp's instruction stream
        if (o < FIN) rr[o] = tk_lane;
    } else {
#pragma unroll
        for (int f = 0; f < FIN; f++)
            acc += rr[f] * Wsh[f * NFOUT + o];
    }
    out[(size_t)v * NFOUT + o] = acc;
}

// ---------------------------------------------------------------------------
// SpMM scatter: t[rows[e], :] += vals[e] * z[cols[e], :]
// one thread per (edge, float4 chunk)
// ---------------------------------------------------------------------------
template<int FIN>
__global__ void scatter_kernel(const int* __restrict__ rows, const int* __restrict__ cols,
                               const float* __restrict__ vals, const float* __restrict__ z,
                               float* __restrict__ t, int nedges) {
    constexpr int CH = FIN / 4;
    int tid = blockIdx.x * blockDim.x + threadIdx.x;
    if (tid >= nedges * CH) return;
    int e = tid / CH;
    int c = tid % CH;
    int r  = rows[e];
    int ci = cols[e];
    float vv = vals[e];
    float4 zv = *(const float4*)(z + (size_t)ci * FIN + c * 4);
    float* tp = t + (size_t)r * FIN + c * 4;
    atomicAdd(tp + 0, vv * zv.x);
    atomicAdd(tp + 1, vv * zv.y);
    atomicAdd(tp + 2, vv * zv.z);
    atomicAdd(tp + 3, vv * zv.w);
}

__global__ void elu_kernel(float* __restrict__ a, int n) {
    int i = blockIdx.x * blockDim.x + threadIdx.x;
    if (i < n) {
        float v = a[i];
        a[i] = v > 0.0f ? v : expm1f(v);
    }
}

__global__ void pool_kernel(const float* __restrict__ skip, float* __restrict__ pooled) {
    int i = blockIdx.x * blockDim.x + threadIdx.x;  // (NV/4) * 8 float4 chunks
    if (i >= (NV / 4) * 8) return;
    int p = i >> 3, c = i & 7;
    const float4* base = (const float4*)(skip + (size_t)p * 4 * NFOUT) + c;
    float4 m = base[0];
#pragma unroll
    for (int j = 1; j < 4; j++) {
        float4 v = base[j * 8];
        m.x = fmaxf(m.x, v.x);
        m.y = fmaxf(m.y, v.y);
        m.z = fmaxf(m.z, v.z);
        m.w = fmaxf(m.w, v.w);
    }
    ((float4*)pooled)[(size_t)p * 8 + c] = m;
}

// ---------------------------------------------------------------------------
// Host-side layer driver
// ---------------------------------------------------------------------------
template<int FIN>
static void run_layer(const float* xin, const float* W, const float* bias, float* out,
                      float* t0, float* t1, float* t2,
                      const int* rows, const int* cols, const float* vals, int nedges) {
    const int TPB = 256;
    const int vwarp_blocks = (NV * 32 + TPB - 1) / TPB;        // warp-per-vertex kernels
    const int sc_total = nedges * (FIN / 4);
    const int sc_blocks = (sc_total + TPB - 1) / TPB;
    const size_t tbytes = (size_t)NV * FIN * sizeof(float);

    // k = 0
    gemm_init_kernel<FIN><<<vwarp_blocks, TPB>>>(xin, W, bias, out);
    // k = 1: t1 = L x
    cudaMemsetAsync(t1, 0, tbytes);
    scatter_kernel<FIN><<<sc_blocks, TPB>>>(rows, cols, vals, xin, t1, nedges);
    combine_gemm_kernel<FIN><<<vwarp_blocks, TPB>>>(t1, nullptr, W, out, 1);
    // k = 2: t2 = 2 L t1 - x
    cudaMemsetAsync(t2, 0, tbytes);
    scatter_kernel<FIN><<<sc_blocks, TPB>>>(rows, cols, vals, t1, t2, nedges);
    combine_gemm_kernel<FIN><<<vwarp_blocks, TPB>>>(t2, xin, W, out, 2);
    // k = 3: t3 = 2 L t2 - t1   (stored into t0)
    cudaMemsetAsync(t0, 0, tbytes);
    scatter_kernel<FIN><<<sc_blocks, TPB>>>(rows, cols, vals, t2, t0, nedges);
    combine_gemm_kernel<FIN><<<vwarp_blocks, TPB>>>(t0, t1, W, out, 3);
    // k = 4: t4 = 2 L t3 - t2   (stored into t1, overwriting stale t1)
    cudaMemsetAsync(t1, 0, tbytes);
    scatter_kernel<FIN><<<sc_blocks, TPB>>>(rows, cols, vals, t0, t1, nedges);
    combine_gemm_kernel<FIN><<<vwarp_blocks, TPB>>>(t1, t2, W, out, 4);
}

extern "C" void kernel_launch(void* const* d_in, const int* in_sizes, int n_in,
                              void* d_out, int out_size) {
    const float* x    = (const float*)d_in[0];
    const int*   rows = (const int*)  d_in[1];
    const int*   cols = (const int*)  d_in[2];
    const float* vals = (const float*)d_in[3];
    const float* w1   = (const float*)d_in[4];
    const float* b1   = (const float*)d_in[5];
    const float* w2   = (const float*)d_in[6];
    const float* b2   = (const float*)d_in[7];
    int nedges = in_sizes[1];

    float* skip   = (float*)d_out;                 // [NV, 32]
    float* pooled = skip + (size_t)NV * NFOUT;     // [NV/4, 32]

    float *t0, *t1, *t2, *h;
    cudaGetSymbolAddress((void**)&t0, g_t0);
    cudaGetSymbolAddress((void**)&t1, g_t1);
    cudaGetSymbolAddress((void**)&t2, g_t2);
    cudaGetSymbolAddress((void**)&h,  g_h);

    const int TPB = 256;
    int n_h = NV * NFOUT;
    int elu_blocks = (n_h + TPB - 1) / TPB;

    // Layer 1: ChebConv(16 -> 32), then ELU (into h)
    run_layer<16>(x, w1, b1, h, t0, t1, t2, rows, cols, vals, nedges);
    elu_kernel<<<elu_blocks, TPB>>>(h, n_h);

    // Layer 2: ChebConv(32 -> 32) accumulated straight into d_out skip region, then ELU
    run_layer<32>(h, w2, b2, skip, t0, t1, t2, rows, cols, vals, nedges);
    elu_kernel<<<elu_blocks, TPB>>>(skip, n_h);

    // Factor-4 vertex max pool
    int pool_total = (NV / 4) * 8;
    pool_kernel<<<(pool_total + TPB - 1) / TPB, TPB>>>(skip, pooled);
}

// round 2
// speedup vs baseline: 1.2486x; 1.2486x over previous
#include <cuda_runtime.h>
#include <math.h>

#define NV 786432
#define KS 5

// Scratch (static device globals; no allocations allowed)
__device__ float g_b1[(size_t)NV * 32];
__device__ float g_b2[(size_t)NV * 32];
__device__ float g_b3[(size_t)NV * 32];
__device__ float g_b4[(size_t)NV * 32];
__device__ float g_h [(size_t)NV * 32];

// ---------------------------------------------------------------------------
// SpMM scatter: t[rows[e], :] += scale * vals[e] * z[cols[e], :]
// one thread per edge; vectorized red.global.add.v4.f32
// ---------------------------------------------------------------------------
template<int FIN>
__global__ void scatter_kernel(const int* __restrict__ rows, const int* __restrict__ cols,
                               const float* __restrict__ vals, const float* __restrict__ z,
                               float* __restrict__ t, int nedges, float scale) {
    int e = blockIdx.x * blockDim.x + threadIdx.x;
    if (e >= nedges) return;
    int r  = __ldg(rows + e);
    int ci = __ldg(cols + e);
    float vv = scale * __ldg(vals + e);
    const float4* zp = (const float4*)(z + (size_t)ci * FIN);
    float* tp = t + (size_t)r * FIN;
#pragma unroll
    for (int c = 0; c < FIN / 4; c++) {
        float4 zv = __ldg(zp + c);
        asm volatile("red.global.add.v4.f32 [%0], {%1, %2, %3, %4};"
                     :: "l"(tp + c * 4),
                        "f"(vv * zv.x), "f"(vv * zv.y), "f"(vv * zv.z), "f"(vv * zv.w)
                     : "memory");
    }
}

// ---------------------------------------------------------------------------
// t = -prev  (pre-init so scatter with scale=2 yields t = 2*L*z - prev)
// ---------------------------------------------------------------------------
__global__ void neg_init_kernel(float* __restrict__ t, const float* __restrict__ prev, int n4) {
    int i = blockIdx.x * blockDim.x + threadIdx.x;
    if (i >= n4) return;
    float4 p = ((const float4*)prev)[i];
    ((float4*)t)[i] = make_float4(-p.x, -p.y, -p.z, -p.w);
}

// ---------------------------------------------------------------------------
// Fused 5-term GEMM + bias + ELU (+ optional factor-4 max pool).
// Block = 128 threads = 4 warps = 4 consecutive vertices; lane = out channel.
// W layout: [FIN*KS, 32] with row index f*KS + k.
// ---------------------------------------------------------------------------
template<int FIN, bool DOPOOL>
__global__ void gemm5_kernel(const float* __restrict__ t0, const float* __restrict__ t1,
                             const float* __restrict__ t2, const float* __restrict__ t3,
                             const float* __restrict__ t4,
                             const float* __restrict__ W, const float* __restrict__ bias,
                             float* __restrict__ out, float* __restrict__ pooled) {
    __shared__ float Wsh[KS * FIN * 32];
    __shared__ float rowbuf[128];
    int tid = threadIdx.x;
    for (int i = tid; i < KS * FIN * 32; i += 128) {
        int fk = i >> 5, o = i & 31;
        int f = fk / KS, k = fk % KS;
        Wsh[(k * FIN + f) * 32 + o] = W[i];
    }
    __syncthreads();

    int v = blockIdx.x * 4 + (tid >> 5);
    int o = tid & 31;
    float acc = __ldg(bias + o);

    const float* ts[KS] = {t0, t1, t2, t3, t4};
#pragma unroll
    for (int k = 0; k < KS; k++) {
        const float4* tr4 = (const float4*)(ts[k] + (size_t)v * FIN);
        const float* wk = Wsh + k * FIN * 32 + o;
#pragma unroll
        for (int f4 = 0; f4 < FIN / 4; f4++) {
            float4 tv = __ldg(tr4 + f4);
            acc += tv.x * wk[(f4 * 4 + 0) * 32];
            acc += tv.y * wk[(f4 * 4 + 1) * 32];
            acc += tv.z * wk[(f4 * 4 + 2) * 32];
            acc += tv.w * wk[(f4 * 4 + 3) * 32];
        }
    }
    acc = acc > 0.0f ? acc : expm1f(acc);
    out[(size_t)v * 32 + o] = acc;

    if (DOPOOL) {
        rowbuf[tid] = acc;
        __syncthreads();
        if (tid < 32) {
            float m = fmaxf(fmaxf(rowbuf[o], rowbuf[32 + o]),
                            fmaxf(rowbuf[64 + o], rowbuf[96 + o]));
            pooled[(size_t)blockIdx.x * 32 + o] = m;
        }
    }
}

// ---------------------------------------------------------------------------
// Host-side layer driver:
//   t1 = L x
//   t2 = 2 L t1 - x       (init t2 = -x,  scatter scale 2)
//   t3 = 2 L t2 - t1
//   t4 = 2 L t3 - t2
//   out = ELU( [x t1 t2 t3 t4] @ W + b )   (+ pool for layer 2)
// ---------------------------------------------------------------------------
template<int FIN, bool DOPOOL>
static void run_layer(const float* xin, const float* W, const float* bias,
                      float* out, float* pooled,
                      float* t1, float* t2, float* t3, float* t4,
                      const int* rows, const int* cols, const float* vals, int nedges) {
    const int TPB = 256;
    const int sc_blocks = (nedges + TPB - 1) / TPB;
    const int n4 = NV * FIN / 4;
    const int in_blocks = (n4 + TPB - 1) / TPB;
    const size_t tbytes = (size_t)NV * FIN * sizeof(float);

    cudaMemsetAsync(t1, 0, tbytes);
    scatter_kernel<FIN><<<sc_blocks, TPB>>>(rows, cols, vals, xin, t1, nedges, 1.0f);

    neg_init_kernel<<<in_blocks, TPB>>>(t2, xin, n4);
    scatter_kernel<FIN><<<sc_blocks, TPB>>>(rows, cols, vals, t1, t2, nedges, 2.0f);

    neg_init_kernel<<<in_blocks, TPB>>>(t3, t1, n4);
    scatter_kernel<FIN><<<sc_blocks, TPB>>>(rows, cols, vals, t2, t3, nedges, 2.0f);

    neg_init_kernel<<<in_blocks, TPB>>>(t4, t2, n4);
    scatter_kernel<FIN><<<sc_blocks, TPB>>>(rows, cols, vals, t3, t4, nedges, 2.0f);

    gemm5_kernel<FIN, DOPOOL><<<NV / 4, 128>>>(xin, t1, t2, t3, t4, W, bias, out, pooled);
}

extern "C" void kernel_launch(void* const* d_in, const int* in_sizes, int n_in,
                              void* d_out, int out_size) {
    const float* x    = (const float*)d_in[0];
    const int*   rows = (const int*)  d_in[1];
    const int*   cols = (const int*)  d_in[2];
    const float* vals = (const float*)d_in[3];
    const float* w1   = (const float*)d_in[4];
    const float* b1   = (const float*)d_in[5];
    const float* w2   = (const float*)d_in[6];
    const float* b2   = (const float*)d_in[7];
    int nedges = in_sizes[1];

    float* skip   = (float*)d_out;              // [NV, 32]
    float* pooled = skip + (size_t)NV * 32;     // [NV/4, 32]

    float *b1p, *b2p, *b3p, *b4p, *h;
    cudaGetSymbolAddress((void**)&b1p, g_b1);
    cudaGetSymbolAddress((void**)&b2p, g_b2);
    cudaGetSymbolAddress((void**)&b3p, g_b3);
    cudaGetSymbolAddress((void**)&b4p, g_b4);
    cudaGetSymbolAddress((void**)&h,   g_h);

    // Layer 1: ChebConv(16 -> 32) + ELU  -> h
    run_layer<16, false>(x, w1, b1, h, nullptr, b1p, b2p, b3p, b4p,
                         rows, cols, vals, nedges);

    // Layer 2: ChebConv(32 -> 32) + ELU -> skip, fused pool -> pooled
    run_layer<32, true>(h, w2, b2, skip, pooled, b1p, b2p, b3p, b4p,
                        rows, cols, vals, nedges);
}

// round 3
// speedup vs baseline: 1.5245x; 1.2210x over previous
#include <cuda_runtime.h>
#include <math.h>

#define NV 786432
#define KS 5
#define EMAX (8 * NV)

// ---- static device scratch (no allocations allowed) ----
__device__ float g_t1[(size_t)NV * 32];
__device__ float g_t2[(size_t)NV * 32];
__device__ float g_t3[(size_t)NV * 32];
__device__ float g_t4[(size_t)NV * 32];
__device__ float g_h [(size_t)NV * 32];
__device__ int   g_deg[NV];
__device__ int   g_excl[NV];
__device__ int   g_rowptr[NV + 1];
__device__ int   g_pos[NV];
__device__ int   g_bsum[256];
__device__ int   g_ecol[EMAX];
__device__ float g_eval[EMAX];

// ===========================================================================
// CSR build
// ===========================================================================
__global__ void hist_kernel(const int* __restrict__ rows, int* __restrict__ deg, int nedges) {
    int e = blockIdx.x * blockDim.x + threadIdx.x;
    if (e < nedges) atomicAdd(deg + __ldg(rows + e), 1);
}

// 192 blocks x 1024 threads x 4 elems: per-block exclusive scan + block totals
__global__ void scan_local_kernel(const int* __restrict__ deg, int* __restrict__ excl,
                                  int* __restrict__ bsum) {
    __shared__ int warp_sums[32];
    int t = threadIdx.x;
    int base = blockIdx.x * 4096 + t * 4;
    int4 d = *(const int4*)(deg + base);
    int tsum = d.x + d.y + d.z + d.w;
    int lane = t & 31, wid = t >> 5;
    int v = tsum;
#pragma unroll
    for (int o = 1; o < 32; o <<= 1) {
        int n = __shfl_up_sync(~0u, v, o);
        if (lane >= o) v += n;
    }
    if (lane == 31) warp_sums[wid] = v;
    __syncthreads();
    if (wid == 0) {
        int ws = warp_sums[lane];
#pragma unroll
        for (int o = 1; o < 32; o <<= 1) {
            int n = __shfl_up_sync(~0u, ws, o);
            if (lane >= o) ws += n;
        }
        warp_sums[lane] = ws;
    }
    __syncthreads();
    int warp_off = (wid == 0) ? 0 : warp_sums[wid - 1];
    int e0 = warp_off + v - tsum;  // exclusive prefix of this thread within block
    excl[base + 0] = e0;
    excl[base + 1] = e0 + d.x;
    excl[base + 2] = e0 + d.x + d.y;
    excl[base + 3] = e0 + d.x + d.y + d.z;
    if (t == 0) bsum[blockIdx.x] = 0;  // overwritten below; keeps [192..256) zero users safe
    __syncthreads();
    if (t == 0) bsum[blockIdx.x] = warp_sums[31];
}

// single block: exclusive scan of 192 block sums (padded to 256)
__global__ void scan_bsum_kernel(int* __restrict__ bsum) {
    __shared__ int s[256];
    int t = threadIdx.x;
    s[t] = (t < 192) ? bsum[t] : 0;
    __syncthreads();
#pragma unroll
    for (int o = 1; o < 256; o <<= 1) {
        int add = (t >= o) ? s[t - o] : 0;
        __syncthreads();
        s[t] += add;
        __syncthreads();
    }
    if (t < 192) bsum[t] = (t == 0) ? 0 : s[t - 1];
}

__global__ void finalize_rowptr_kernel(const int* __restrict__ excl, const int* __restrict__ bsum,
                                       int* __restrict__ rowptr, int* __restrict__ pos, int nedges) {
    int i = blockIdx.x * blockDim.x + threadIdx.x;
    if (i >= NV) return;
    int r = excl[i] + bsum[i >> 12];  // 4096 elems per scan block
    rowptr[i] = r;
    pos[i] = r;
    if (i == 0) rowptr[NV] = nedges;
}

__global__ void fill_kernel(const int* __restrict__ rows, const int* __restrict__ cols,
                            const float* __restrict__ vals, int* __restrict__ pos,
                            int* __restrict__ ecol, float* __restrict__ eval, int nedges) {
    int e = blockIdx.x * blockDim.x + threadIdx.x;
    if (e >= nedges) return;
    int r = __ldg(rows + e);
    int p = atomicAdd(pos + r, 1);
    ecol[p] = __ldg(cols + e);
    eval[p] = __ldg(vals + e);
}

// ===========================================================================
// Gather SpMM with fused Chebyshev recurrence:
//   t[v,:] = scale * sum_j val_j * z[col_j,:]  -  (prev ? prev[v,:] : 0)
// FIN lanes cooperate on one row.
// ===========================================================================
template<int FIN>
__global__ void spmm_gather_kernel(const int* __restrict__ rowptr, const int* __restrict__ ecol,
                                   const float* __restrict__ eval, const float* __restrict__ z,
                                   const float* __restrict__ prev, float scale,
                                   float* __restrict__ t) {
    int v = (blockIdx.x * blockDim.x + threadIdx.x) / FIN;
    int f = threadIdx.x % FIN;
    if (v >= NV) return;
    int j = __ldg(rowptr + v), jend = __ldg(rowptr + v + 1);
    float acc = 0.0f;
    for (; j + 1 < jend; j += 2) {
        int c0 = __ldg(ecol + j);
        int c1 = __ldg(ecol + j + 1);
        float w0 = __ldg(eval + j);
        float w1 = __ldg(eval + j + 1);
        float z0 = __ldg(z + (size_t)c0 * FIN + f);
        float z1 = __ldg(z + (size_t)c1 * FIN + f);
        acc += w0 * z0 + w1 * z1;
    }
    if (j < jend) {
        int c = __ldg(ecol + j);
        acc += __ldg(eval + j) * __ldg(z + (size_t)c * FIN + f);
    }
    acc *= scale;
    if (prev) acc -= __ldg(prev + (size_t)v * FIN + f);
    t[(size_t)v * FIN + f] = acc;
}

// ===========================================================================
// Fused 5-term GEMM + bias + ELU (+ optional factor-4 max pool)
// ===========================================================================
template<int FIN, bool DOPOOL>
__global__ void gemm5_kernel(const float* __restrict__ t0, const float* __restrict__ t1,
                             const float* __restrict__ t2, const float* __restrict__ t3,
                             const float* __restrict__ t4,
                             const float* __restrict__ W, const float* __restrict__ bias,
                             float* __restrict__ out, float* __restrict__ pooled) {
    __shared__ float Wsh[KS * FIN * 32];
    __shared__ float rowbuf[128];
    int tid = threadIdx.x;
    for (int i = tid; i < KS * FIN * 32; i += 128) {
        int fk = i >> 5, o = i & 31;
        int f = fk / KS, k = fk % KS;
        Wsh[(k * FIN + f) * 32 + o] = W[i];
    }
    __syncthreads();

    int v = blockIdx.x * 4 + (tid >> 5);
    int o = tid & 31;
    float acc = __ldg(bias + o);

    const float* ts[KS] = {t0, t1, t2, t3, t4};
#pragma unroll
    for (int k = 0; k < KS; k++) {
        const float4* tr4 = (const float4*)(ts[k] + (size_t)v * FIN);
        const float* wk = Wsh + k * FIN * 32 + o;
#pragma unroll
        for (int f4 = 0; f4 < FIN / 4; f4++) {
            float4 tv = __ldg(tr4 + f4);
            acc += tv.x * wk[(f4 * 4 + 0) * 32];
            acc += tv.y * wk[(f4 * 4 + 1) * 32];
            acc += tv.z * wk[(f4 * 4 + 2) * 32];
            acc += tv.w * wk[(f4 * 4 + 3) * 32];
        }
    }
    acc = acc > 0.0f ? acc : expm1f(acc);
    out[(size_t)v * 32 + o] = acc;

    if (DOPOOL) {
        rowbuf[tid] = acc;
        __syncthreads();
        if (tid < 32) {
            float m = fmaxf(fmaxf(rowbuf[o], rowbuf[32 + o]),
                            fmaxf(rowbuf[64 + o], rowbuf[96 + o]));
            pooled[(size_t)blockIdx.x * 32 + o] = m;
        }
    }
}

// ===========================================================================
// Host-side layer driver
// ===========================================================================
template<int FIN, bool DOPOOL>
static void run_layer(const float* xin, const float* W, const float* bias,
                      float* out, float* pooled,
                      float* t1, float* t2, float* t3, float* t4,
                      const int* rowptr, const int* ecol, const float* eval) {
    const int TPB = 256;
    const int spmm_blocks = (NV * FIN + TPB - 1) / TPB;

    spmm_gather_kernel<FIN><<<spmm_blocks, TPB>>>(rowptr, ecol, eval, xin, nullptr, 1.0f, t1);
    spmm_gather_kernel<FIN><<<spmm_blocks, TPB>>>(rowptr, ecol, eval, t1,  xin,     2.0f, t2);
    spmm_gather_kernel<FIN><<<spmm_blocks, TPB>>>(rowptr, ecol, eval, t2,  t1,      2.0f, t3);
    spmm_gather_kernel<FIN><<<spmm_blocks, TPB>>>(rowptr, ecol, eval, t3,  t2,      2.0f, t4);

    gemm5_kernel<FIN, DOPOOL><<<NV / 4, 128>>>(xin, t1, t2, t3, t4, W, bias, out, pooled);
}

extern "C" void kernel_launch(void* const* d_in, const int* in_sizes, int n_in,
                              void* d_out, int out_size) {
    const float* x    = (const float*)d_in[0];
    const int*   rows = (const int*)  d_in[1];
    const int*   cols = (const int*)  d_in[2];
    const float* vals = (const float*)d_in[3];
    const float* w1   = (const float*)d_in[4];
    const float* b1   = (const float*)d_in[5];
    const float* w2   = (const float*)d_in[6];
    const float* b2   = (const float*)d_in[7];
    int nedges = in_sizes[1];

    float* skip   = (float*)d_out;              // [NV, 32]
    float* pooled = skip + (size_t)NV * 32;     // [NV/4, 32]

    float *t1, *t2, *t3, *t4, *h, *eval;
    int *deg, *excl, *rowptr, *pos, *bsum, *ecol;
    cudaGetSymbolAddress((void**)&t1, g_t1);
    cudaGetSymbolAddress((void**)&t2, g_t2);
    cudaGetSymbolAddress((void**)&t3, g_t3);
    cudaGetSymbolAddress((void**)&t4, g_t4);
    cudaGetSymbolAddress((void**)&h,  g_h);
    cudaGetSymbolAddress((void**)&deg,    g_deg);
    cudaGetSymbolAddress((void**)&excl,   g_excl);
    cudaGetSymbolAddress((void**)&rowptr, g_rowptr);
    cudaGetSymbolAddress((void**)&pos,    g_pos);
    cudaGetSymbolAddress((void**)&bsum,   g_bsum);
    cudaGetSymbolAddress((void**)&ecol,   g_ecol);
    cudaGetSymbolAddress((void**)&eval,   g_eval);

    const int TPB = 256;
    const int eblocks = (nedges + TPB - 1) / TPB;

    // ---- CSR build (per replay; deterministic work) ----
    cudaMemsetAsync(deg, 0, NV * sizeof(int));
    hist_kernel<<<eblocks, TPB>>>(rows, deg, nedges);
    scan_local_kernel<<<NV / 4096, 1024>>>(deg, excl, bsum);
    scan_bsum_kernel<<<1, 256>>>(bsum);
    finalize_rowptr_kernel<<<(NV + TPB - 1) / TPB, TPB>>>(excl, bsum, rowptr, pos, nedges);
    fill_kernel<<<eblocks, TPB>>>(rows, cols, vals, pos, ecol, eval, nedges);

    // ---- Layer 1: ChebConv(16 -> 32) + ELU -> h ----
    run_layer<16, false>(x, w1, b1, h, nullptr, t1, t2, t3, t4, rowptr, ecol, eval);

    // ---- Layer 2: ChebConv(32 -> 32) + ELU -> skip, fused pool -> pooled ----
    run_layer<32, true>(h, w2, b2, skip, pooled, t1, t2, t3, t4, rowptr, ecol, eval);
}

// round 4
// speedup vs baseline: 1.8045x; 1.1837x over previous
#include <cuda_runtime.h>
#include <math.h>

#define NV 786432
#define KS 5
#define EMAX (8 * NV)

// ---- static device scratch (no allocations allowed) ----
__device__ float g_t1[(size_t)NV * 32];
__device__ float g_t2[(size_t)NV * 32];
__device__ float g_t3[(size_t)NV * 32];
__device__ float g_t4[(size_t)NV * 32];
__device__ float g_h [(size_t)NV * 32];
__device__ int   g_deg[NV];
__device__ int   g_excl[NV];
__device__ int   g_rowptr[NV + 1];
__device__ int   g_pos[NV];
__device__ int   g_bsum[256];
__device__ int2  g_edge[EMAX];   // (col, float_as_int(val)) interleaved

// ===========================================================================
// CSR build
// ===========================================================================
__global__ void hist_kernel(const int* __restrict__ rows, int* __restrict__ deg, int nedges) {
    int e = blockIdx.x * blockDim.x + threadIdx.x;
    if (e < nedges) atomicAdd(deg + __ldg(rows + e), 1);
}

// 192 blocks x 1024 threads x 4 elems: per-block exclusive scan + block totals
__global__ void scan_local_kernel(const int* __restrict__ deg, int* __restrict__ excl,
                                  int* __restrict__ bsum) {
    __shared__ int warp_sums[32];
    int t = threadIdx.x;
    int base = blockIdx.x * 4096 + t * 4;
    int4 d = *(const int4*)(deg + base);
    int tsum = d.x + d.y + d.z + d.w;
    int lane = t & 31, wid = t >> 5;
    int v = tsum;
#pragma unroll
    for (int o = 1; o < 32; o <<= 1) {
        int n = __shfl_up_sync(~0u, v, o);
        if (lane >= o) v += n;
    }
    if (lane == 31) warp_sums[wid] = v;
    __syncthreads();
    if (wid == 0) {
        int ws = warp_sums[lane];
#pragma unroll
        for (int o = 1; o < 32; o <<= 1) {
            int n = __shfl_up_sync(~0u, ws, o);
            if (lane >= o) ws += n;
        }
        warp_sums[lane] = ws;
    }
    __syncthreads();
    int warp_off = (wid == 0) ? 0 : warp_sums[wid - 1];
    int e0 = warp_off + v - tsum;  // exclusive prefix of this thread within block
    excl[base + 0] = e0;
    excl[base + 1] = e0 + d.x;
    excl[base + 2] = e0 + d.x + d.y;
    excl[base + 3] = e0 + d.x + d.y + d.z;
    __syncthreads();
    if (t == 0) bsum[blockIdx.x] = warp_sums[31];
}

// single block: exclusive scan of 192 block sums (padded to 256)
__global__ void scan_bsum_kernel(int* __restrict__ bsum) {
    __shared__ int s[256];
    int t = threadIdx.x;
    s[t] = (t < 192) ? bsum[t] : 0;
    __syncthreads();
#pragma unroll
    for (int o = 1; o < 256; o <<= 1) {
        int add = (t >= o) ? s[t - o] : 0;
        __syncthreads();
        s[t] += add;
        __syncthreads();
    }
    if (t < 192) bsum[t] = (t == 0) ? 0 : s[t - 1];
}

__global__ void finalize_rowptr_kernel(const int* __restrict__ excl, const int* __restrict__ bsum,
                                       int* __restrict__ rowptr, int* __restrict__ pos, int nedges) {
    int i = blockIdx.x * blockDim.x + threadIdx.x;
    if (i >= NV) return;
    int r = excl[i] + bsum[i >> 12];  // 4096 elems per scan block
    rowptr[i] = r;
    pos[i] = r;
    if (i == 0) rowptr[NV] = nedges;
}

__global__ void fill_kernel(const int* __restrict__ rows, const int* __restrict__ cols,
                            const float* __restrict__ vals, int* __restrict__ pos,
                            int2* __restrict__ edge, int nedges) {
    int e = blockIdx.x * blockDim.x + threadIdx.x;
    if (e >= nedges) return;
    int r = __ldg(rows + e);
    int p = atomicAdd(pos + r, 1);
    edge[p] = make_int2(__ldg(cols + e), __float_as_int(__ldg(vals + e)));
}

// ===========================================================================
// Gather SpMM with fused Chebyshev recurrence:
//   t[v,:] = scale * sum_j val_j * z[col_j,:]  -  (prev ? prev[v,:] : 0)
// LPR = FIN/4 lanes per row; each lane owns one float4 slice.
// Edge loop unrolled x4 for MLP=8 (4 int2 + 4 float4 loads in flight).
// ===========================================================================
template<int FIN>
__global__ void spmm_kernel(const int* __restrict__ rowptr, const int2* __restrict__ edge,
                            const float* __restrict__ z, const float* __restrict__ prev,
                            float scale, float* __restrict__ t) {
    constexpr int LPR = FIN / 4;
    int tid = blockIdx.x * blockDim.x + threadIdx.x;
    int v  = tid / LPR;
    int f4 = tid % LPR;
    if (v >= NV) return;
    int j = __ldg(rowptr + v), jend = __ldg(rowptr + v + 1);
    const float4* z4 = (const float4*)z;
    float4 acc = make_float4(0.f, 0.f, 0.f, 0.f);

    for (; j + 4 <= jend; j += 4) {
        int2 e0 = __ldg(edge + j);
        int2 e1 = __ldg(edge + j + 1);
        int2 e2 = __ldg(edge + j + 2);
        int2 e3 = __ldg(edge + j + 3);
        float4 z0 = __ldg(z4 + (size_t)e0.x * LPR + f4);
        float4 z1 = __ldg(z4 + (size_t)e1.x * LPR + f4);
        float4 z2 = __ldg(z4 + (size_t)e2.x * LPR + f4);
        float4 z3 = __ldg(z4 + (size_t)e3.x * LPR + f4);
        float w0 = __int_as_float(e0.y), w1 = __int_as_float(e1.y);
        float w2 = __int_as_float(e2.y), w3 = __int_as_float(e3.y);
        acc.x += w0 * z0.x; acc.y += w0 * z0.y; acc.z += w0 * z0.z; acc.w += w0 * z0.w;
        acc.x += w1 * z1.x; acc.y += w1 * z1.y; acc.z += w1 * z1.z; acc.w += w1 * z1.w;
        acc.x += w2 * z2.x; acc.y += w2 * z2.y; acc.z += w2 * z2.z; acc.w += w2 * z2.w;
        acc.x += w3 * z3.x; acc.y += w3 * z3.y; acc.z += w3 * z3.z; acc.w += w3 * z3.w;
    }
    for (; j < jend; j++) {
        int2 e = __ldg(edge + j);
        float4 zv = __ldg(z4 + (size_t)e.x * LPR + f4);
        float w = __int_as_float(e.y);
        acc.x += w * zv.x; acc.y += w * zv.y; acc.z += w * zv.z; acc.w += w * zv.w;
    }

    acc.x *= scale; acc.y *= scale; acc.z *= scale; acc.w *= scale;
    if (prev) {
        float4 p = __ldg((const float4*)prev + (size_t)v * LPR + f4);
        acc.x -= p.x; acc.y -= p.y; acc.z -= p.z; acc.w -= p.w;
    }
    ((float4*)t)[(size_t)v * LPR + f4] = acc;
}

// ===========================================================================
// Fused 5-term GEMM + bias + ELU (+ optional factor-4 max pool)
// ===========================================================================
template<int FIN, bool DOPOOL>
__global__ void gemm5_kernel(const float* __restrict__ t0, const float* __restrict__ t1,
                             const float* __restrict__ t2, const float* __restrict__ t3,
                             const float* __restrict__ t4,
                             const float* __restrict__ W, const float* __restrict__ bias,
                             float* __restrict__ out, float* __restrict__ pooled) {
    __shared__ float Wsh[KS * FIN * 32];
    __shared__ float rowbuf[128];
    int tid = threadIdx.x;
    for (int i = tid; i < KS * FIN * 32; i += 128) {
        int fk = i >> 5, o = i & 31;
        int f = fk / KS, k = fk % KS;
        Wsh[(k * FIN + f) * 32 + o] = W[i];
    }
    __syncthreads();

    int v = blockIdx.x * 4 + (tid >> 5);
    int o = tid & 31;
    float acc = __ldg(bias + o);

    const float* ts[KS] = {t0, t1, t2, t3, t4};
#pragma unroll
    for (int k = 0; k < KS; k++) {
        const float4* tr4 = (const float4*)(ts[k] + (size_t)v * FIN);
        const float* wk = Wsh + k * FIN * 32 + o;
#pragma unroll
        for (int f4 = 0; f4 < FIN / 4; f4++) {
            float4 tv = __ldg(tr4 + f4);
            acc += tv.x * wk[(f4 * 4 + 0) * 32];
            acc += tv.y * wk[(f4 * 4 + 1) * 32];
            acc += tv.z * wk[(f4 * 4 + 2) * 32];
            acc += tv.w * wk[(f4 * 4 + 3) * 32];
        }
    }
    acc = acc > 0.0f ? acc : expm1f(acc);
    out[(size_t)v * 32 + o] = acc;

    if (DOPOOL) {
        rowbuf[tid] = acc;
        __syncthreads();
        if (tid < 32) {
            float m = fmaxf(fmaxf(rowbuf[o], rowbuf[32 + o]),
                            fmaxf(rowbuf[64 + o], rowbuf[96 + o]));
            pooled[(size_t)blockIdx.x * 32 + o] = m;
        }
    }
}

// ===========================================================================
// Host-side layer driver
// ===========================================================================
template<int FIN, bool DOPOOL>
static void run_layer(const float* xin, const float* W, const float* bias,
                      float* out, float* pooled,
                      float* t1, float* t2, float* t3, float* t4,
                      const int* rowptr, const int2* edge) {
    const int TPB = 256;
    const int spmm_threads = NV * (FIN / 4);
    const int spmm_blocks = (spmm_threads + TPB - 1) / TPB;

    spmm_kernel<FIN><<<spmm_blocks, TPB>>>(rowptr, edge, xin, nullptr, 1.0f, t1);
    spmm_kernel<FIN><<<spmm_blocks, TPB>>>(rowptr, edge, t1,  xin,     2.0f, t2);
    spmm_kernel<FIN><<<spmm_blocks, TPB>>>(rowptr, edge, t2,  t1,      2.0f, t3);
    spmm_kernel<FIN><<<spmm_blocks, TPB>>>(rowptr, edge, t3,  t2,      2.0f, t4);

    gemm5_kernel<FIN, DOPOOL><<<NV / 4, 128>>>(xin, t1, t2, t3, t4, W, bias, out, pooled);
}

extern "C" void kernel_launch(void* const* d_in, const int* in_sizes, int n_in,
                              void* d_out, int out_size) {
    const float* x    = (const float*)d_in[0];
    const int*   rows = (const int*)  d_in[1];
    const int*   cols = (const int*)  d_in[2];
    const float* vals = (const float*)d_in[3];
    const float* w1   = (const float*)d_in[4];
    const float* b1   = (const float*)d_in[5];
    const float* w2   = (const float*)d_in[6];
    const float* b2   = (const float*)d_in[7];
    int nedges = in_sizes[1];

    float* skip   = (float*)d_out;              // [NV, 32]
    float* pooled = skip + (size_t)NV * 32;     // [NV/4, 32]

    float *t1, *t2, *t3, *t4, *h;
    int *deg, *excl, *rowptr, *pos, *bsum;
    int2* edge;
    cudaGetSymbolAddress((void**)&t1, g_t1);
    cudaGetSymbolAddress((void**)&t2, g_t2);
    cudaGetSymbolAddress((void**)&t3, g_t3);
    cudaGetSymbolAddress((void**)&t4, g_t4);
    cudaGetSymbolAddress((void**)&h,  g_h);
    cudaGetSymbolAddress((void**)&deg,    g_deg);
    cudaGetSymbolAddress((void**)&excl,   g_excl);
    cudaGetSymbolAddress((void**)&rowptr, g_rowptr);
    cudaGetSymbolAddress((void**)&pos,    g_pos);
    cudaGetSymbolAddress((void**)&bsum,   g_bsum);
    cudaGetSymbolAddress((void**)&edge,   g_edge);

    const int TPB = 256;
    const int eblocks = (nedges + TPB - 1) / TPB;

    // ---- CSR build (per replay; deterministic work) ----
    cudaMemsetAsync(deg, 0, NV * sizeof(int));
    hist_kernel<<<eblocks, TPB>>>(rows, deg, nedges);
    scan_local_kernel<<<NV / 4096, 1024>>>(deg, excl, bsum);
    scan_bsum_kernel<<<1, 256>>>(bsum);
    finalize_rowptr_kernel<<<(NV + TPB - 1) / TPB, TPB>>>(excl, bsum, rowptr, pos, nedges);
    fill_kernel<<<eblocks, TPB>>>(rows, cols, vals, pos, edge, nedges);

    // ---- Layer 1: ChebConv(16 -> 32) + ELU -> h ----
    run_layer<16, false>(x, w1, b1, h, nullptr, t1, t2, t3, t4, rowptr, edge);

    // ---- Layer 2: ChebConv(32 -> 32) + ELU -> skip, fused pool -> pooled ----
    run_layer<32, true>(h, w2, b2, skip, pooled, t1, t2, t3, t4, rowptr, edge);
}